// round 13
// baseline (speedup 1.0000x reference)
#include <cuda_runtime.h>

#define HH 256
#define WW 256
#define KTOP 10
#define RADIUS 0.015f
#define RR2 (RADIUS * RADIUS)
#define EPSD 1e-4f
#define NP 20000

// 8x4 pixel tiles, one warp per tile
#define TSHX 3
#define TSHY 2
#define TGX (WW >> TSHX)      // 32 tiles in x
#define TGY (HH >> TSHY)      // 64 tiles in y
#define NTILES (TGX * TGY)    // 2048
#define CAP 128               // entries per tile (mean ~44, +12 sigma)

typedef unsigned long long u64;
typedef unsigned int u32;

// ---------------- scratch (no allocations allowed) ----------------
__device__ int    g_count[NTILES];          // zero-init; re-zeroed by k_render
__device__ float4 g_bin[NTILES * CAP];      // {x_ndc, y_ndc, z, idx-as-float}

// -------------------------------------------------------------------
// Fused projection + tile binning. Footprint: <=2 tiles in x (8px tiles),
// <=3 tiles in y (4px tiles, splat spans up to ~5.9 px). All candidate
// atomics issued independently (MLP) before any store.
__global__ void __launch_bounds__(128) k_bin(const float* __restrict__ pts,
                                             const float* __restrict__ Rm,
                                             const float* __restrict__ Tv,
                                             const float* __restrict__ focal,
                                             const float* __restrict__ pp) {
    int p = blockIdx.x * blockDim.x + threadIdx.x;
    if (p >= NP) return;
    float px = pts[3 * p + 0];
    float py = pts[3 * p + 1];
    float pz = pts[3 * p + 2];
    // pc = points @ R + T (row-vector * matrix): pc_j = sum_i p_i * R[i][j]
    float cx = fmaf(px, __ldg(Rm + 0), fmaf(py, __ldg(Rm + 3), fmaf(pz, __ldg(Rm + 6), __ldg(Tv + 0))));
    float cy = fmaf(px, __ldg(Rm + 1), fmaf(py, __ldg(Rm + 4), fmaf(pz, __ldg(Rm + 7), __ldg(Tv + 1))));
    float cz = fmaf(px, __ldg(Rm + 2), fmaf(py, __ldg(Rm + 5), fmaf(pz, __ldg(Rm + 8), __ldg(Tv + 2))));
    if (cz <= 0.01f) return;
    float iz = 1.0f / cz;
    float xn = fmaf(__ldg(focal + 0) * cx, iz, __ldg(pp + 0));
    float yn = fmaf(__ldg(focal + 1) * cy, iz, __ldg(pp + 1));

    // pixel w: xs(w) = 1 - (2w+1)/W (decreasing in w). Coverage: |xs - xn| < R.
    float wlo = (1.f - (xn + RADIUS)) * (WW * 0.5f) - 0.5f;
    float whi = (1.f - (xn - RADIUS)) * (WW * 0.5f) - 0.5f;
    int wmin = (int)floorf(wlo);
    int wmax = (int)ceilf(whi);
    float hlo = (1.f - (yn + RADIUS)) * (HH * 0.5f) - 0.5f;
    float hhi = (1.f - (yn - RADIUS)) * (HH * 0.5f) - 0.5f;
    int hmin = (int)floorf(hlo);
    int hmax = (int)ceilf(hhi);
    if (wmax < 0 || wmin > WW - 1 || hmax < 0 || hmin > HH - 1) return;
    wmin = max(wmin, 0); wmax = min(wmax, WW - 1);
    hmin = max(hmin, 0); hmax = min(hmax, HH - 1);
    int tx0 = wmin >> TSHX, tx1 = wmax >> TSHX;   // tx1 - tx0 <= 1
    int ty0 = hmin >> TSHY, ty1 = hmax >> TSHY;   // ty1 - ty0 <= 2

    bool bx = (tx1 != tx0);
    bool by1 = (ty0 + 1 <= ty1);
    bool by2 = (ty0 + 2 <= ty1);

    int r0 = ty0 * TGX;
    int r1 = (ty0 + 1) * TGX;
    int r2 = (ty0 + 2) * TGX;

    // independent atomics first (latencies overlap), stores after
    int pa = atomicAdd(&g_count[r0 + tx0], 1);
    int pb = bx         ? atomicAdd(&g_count[r0 + tx1], 1) : CAP;
    int pc = by1        ? atomicAdd(&g_count[r1 + tx0], 1) : CAP;
    int pd = (by1 && bx)? atomicAdd(&g_count[r1 + tx1], 1) : CAP;
    int pe = by2        ? atomicAdd(&g_count[r2 + tx0], 1) : CAP;
    int pf = (by2 && bx)? atomicAdd(&g_count[r2 + tx1], 1) : CAP;

    float4 e = make_float4(xn, yn, cz, __int_as_float(p));
    if (pa < CAP) g_bin[(r0 + tx0) * CAP + pa] = e;
    if (pb < CAP) g_bin[(r0 + tx1) * CAP + pb] = e;
    if (pc < CAP) g_bin[(r1 + tx0) * CAP + pc] = e;
    if (pd < CAP) g_bin[(r1 + tx1) * CAP + pd] = e;
    if (pe < CAP) g_bin[(r2 + tx0) * CAP + pe] = e;
    if (pf < CAP) g_bin[(r2 + tx1) * CAP + pf] = e;
}

// -------------------------------------------------------------------
// One warp per 8x4 tile; one lane per pixel. Warp-autonomous.
// Rank sort: key = (z_bits<<32)|idx is unique per entry; rank_i = #{key_j < key_i}
// is a bijection to 0..n-1 and equals the (z, lowest-idx) sorted position —
// exactly top_k(-zbuf) order. No shfl chains, no padding, no phases.
__global__ void __launch_bounds__(64) k_render(const float* __restrict__ feats,
                                               float* __restrict__ out) {
    int wrp = threadIdx.x >> 5, lane = threadIdx.x & 31;
    int tile = blockIdx.x * 2 + wrp;
    int txi = tile & (TGX - 1), tyi = tile >> 5;
    int w = (txi << TSHX) + (lane & 7);
    int h = (tyi << TSHY) + (lane >> 3);
    int pix = h * WW + w;

    int n = min(g_count[tile], CAP);
    if (lane == 0 && n) g_count[tile] = 0;   // re-arm for next graph replay

    if (n == 0) {                            // empty tile fast path
        out[pix * 3 + 0] = 0.f;
        out[pix * 3 + 1] = 0.f;
        out[pix * 3 + 2] = 0.f;
        out[HH * WW * 3 + pix] = 0.f;
        out[HH * WW * 4 + pix] = 0.f;
        return;
    }

    float xs = 1.f - (2.f * w + 1.f) * (1.f / WW);
    float ys = 1.f - (2.f * h + 1.f) * (1.f / HH);
    const float4* bin = g_bin + tile * CAP;

    __shared__ float4 s_sh[2][CAP];    // payload, load order
    __shared__ float4 s_sf[2][CAP];    // feature rgb, load order
    __shared__ u64    s_sk[2][CAP];    // keys, load order
    __shared__ float4 s_she[2][CAP];   // payload, sorted order
    __shared__ float4 s_sfe[2][CAP];   // features, sorted order
    float4* SH = s_sh[wrp];
    float4* SF = s_sf[wrp];
    u64*    SK = s_sk[wrp];
    float4* SHE = s_she[wrp];
    float4* SFE = s_sfe[wrp];

    // stage payload + keys (registers + smem) + prefetch features
    u64 V[4];
#pragma unroll
    for (int k = 0; k < 4; k++) {
        int j = k * 32 + lane;
        u64 key = ~0ull;
        if (j < n) {
            float4 e = bin[j];
            SH[j] = e;
            int idx = __float_as_int(e.w);
            key = ((u64)__float_as_uint(e.z) << 32) | (u32)idx;
            SK[j] = key;
            const float* f = feats + 3 * idx;
            SF[j] = make_float4(f[0], f[1], f[2], 0.f);
        }
        V[k] = key;
    }
    __syncwarp();

    // rank computation: broadcast LDS of each key, compare vs registers.
    // nch chunks of 32 entries this lane is responsible for.
    int nch = (n + 31) >> 5;                 // 1..4
    int rk0 = 0, rk1 = 0, rk2 = 0, rk3 = 0;
#pragma unroll 4
    for (int j = 0; j < n; j++) {
        u64 kj = SK[j];                      // broadcast, conflict-free
        rk0 += (kj < V[0]);
        if (nch > 1) rk1 += (kj < V[1]);
        if (nch > 2) rk2 += (kj < V[2]);
        if (nch > 3) rk3 += (kj < V[3]);
    }

    // scatter payload/features into sorted order (ranks are a permutation)
    int rks[4] = {rk0, rk1, rk2, rk3};
#pragma unroll
    for (int k = 0; k < 4; k++) {
        int i = k * 32 + lane;
        if (i < n) {
            int r = rks[k];
            SHE[r] = SH[i];
            SFE[r] = SF[i];
        }
    }
    __syncwarp();

    // streaming front-to-back composite; first KTOP hits == reference top-k
    // (z-ascending, lowest-idx tie-break); running T == cumprod.
    int cnt = 0;
    float T = 1.f, wsum = 0.f, wz = 0.f;
    float r = 0.f, g = 0.f, b = 0.f;
#pragma unroll 4
    for (int j = 0; j < n; j++) {
        float4 e = SHE[j];
        float dx = xs - e.x;
        float dy = ys - e.y;
        float d2 = fmaf(dx, dx, dy * dy);
        if (d2 < RR2 && cnt < KTOP) {
            float wgt = 1.f - d2 * (1.f / RR2);
            float4 f = SFE[j];
            float cw = wgt * T;
            r = fmaf(cw, f.x, r);
            g = fmaf(cw, f.y, g);
            b = fmaf(cw, f.z, b);
            wsum += wgt;
            wz = fmaf(wgt, e.z, wz);
            T *= (1.f - wgt);
            cnt++;
        }
    }

    out[pix * 3 + 0] = fminf(fmaxf(r, 0.f), 1.f);
    out[pix * 3 + 1] = fminf(fmaxf(g, 0.f), 1.f);
    out[pix * 3 + 2] = fminf(fmaxf(b, 0.f), 1.f);
    out[HH * WW * 3 + pix] = 1.f - T;                    // mask
    out[HH * WW * 4 + pix] = wz / fmaxf(wsum, EPSD);     // depth
}

extern "C" void kernel_launch(void* const* d_in, const int* in_sizes, int n_in,
                              void* d_out, int out_size) {
    const float* points    = (const float*)d_in[0];
    const float* features  = (const float*)d_in[1];
    const float* Rm        = (const float*)d_in[2];
    const float* Tv        = (const float*)d_in[3];
    const float* focal     = (const float*)d_in[4];
    const float* principal = (const float*)d_in[5];
    float* out = (float*)d_out;

    k_bin<<<(NP + 127) / 128, 128>>>(points, Rm, Tv, focal, principal);
    k_render<<<NTILES / 2, 64>>>(features, out);
}

// round 14
// speedup vs baseline: 1.1127x; 1.1127x over previous
#include <cuda_runtime.h>

#define HH 256
#define WW 256
#define KTOP 10
#define RADIUS 0.015f
#define RR2 (RADIUS * RADIUS)
#define EPSD 1e-4f
#define NP 20000

// 8x4 pixel tiles, one warp per tile
#define TSHX 3
#define TSHY 2
#define TGX (WW >> TSHX)      // 32 tiles in x
#define TGY (HH >> TSHY)      // 64 tiles in y
#define NTILES (TGX * TGY)    // 2048
#define CAP 128               // entries per tile (mean ~65, +8 sigma)

typedef unsigned long long u64;
typedef unsigned int u32;

// ---------------- scratch (no allocations allowed) ----------------
__device__ int    g_count[NTILES];          // zero-init; re-zeroed by k_render
__device__ float4 g_bin[NTILES * CAP];      // {x_ndc, y_ndc, z, idx-as-float}

// -------------------------------------------------------------------
// Fused projection + tile binning. Footprint: <=2 tiles in x (8px tiles),
// <=3 tiles in y (4px tiles, splat spans up to ~5.9 px). All candidate
// atomics issued independently (MLP) before any store.
__global__ void __launch_bounds__(256) k_bin(const float* __restrict__ pts,
                                             const float* __restrict__ Rm,
                                             const float* __restrict__ Tv,
                                             const float* __restrict__ focal,
                                             const float* __restrict__ pp) {
    int p = blockIdx.x * blockDim.x + threadIdx.x;
    if (p >= NP) return;
    float px = pts[3 * p + 0];
    float py = pts[3 * p + 1];
    float pz = pts[3 * p + 2];
    // pc = points @ R + T (row-vector * matrix): pc_j = sum_i p_i * R[i][j]
    float cx = fmaf(px, __ldg(Rm + 0), fmaf(py, __ldg(Rm + 3), fmaf(pz, __ldg(Rm + 6), __ldg(Tv + 0))));
    float cy = fmaf(px, __ldg(Rm + 1), fmaf(py, __ldg(Rm + 4), fmaf(pz, __ldg(Rm + 7), __ldg(Tv + 1))));
    float cz = fmaf(px, __ldg(Rm + 2), fmaf(py, __ldg(Rm + 5), fmaf(pz, __ldg(Rm + 8), __ldg(Tv + 2))));
    if (cz <= 0.01f) return;
    float iz = 1.0f / cz;
    float xn = fmaf(__ldg(focal + 0) * cx, iz, __ldg(pp + 0));
    float yn = fmaf(__ldg(focal + 1) * cy, iz, __ldg(pp + 1));

    // pixel w: xs(w) = 1 - (2w+1)/W (decreasing in w). Coverage: |xs - xn| < R.
    float wlo = (1.f - (xn + RADIUS)) * (WW * 0.5f) - 0.5f;
    float whi = (1.f - (xn - RADIUS)) * (WW * 0.5f) - 0.5f;
    int wmin = (int)floorf(wlo);
    int wmax = (int)ceilf(whi);
    float hlo = (1.f - (yn + RADIUS)) * (HH * 0.5f) - 0.5f;
    float hhi = (1.f - (yn - RADIUS)) * (HH * 0.5f) - 0.5f;
    int hmin = (int)floorf(hlo);
    int hmax = (int)ceilf(hhi);
    if (wmax < 0 || wmin > WW - 1 || hmax < 0 || hmin > HH - 1) return;
    wmin = max(wmin, 0); wmax = min(wmax, WW - 1);
    hmin = max(hmin, 0); hmax = min(hmax, HH - 1);
    int tx0 = wmin >> TSHX, tx1 = wmax >> TSHX;   // tx1 - tx0 <= 1
    int ty0 = hmin >> TSHY, ty1 = hmax >> TSHY;   // ty1 - ty0 <= 2

    bool bx = (tx1 != tx0);
    bool by1 = (ty0 + 1 <= ty1);
    bool by2 = (ty0 + 2 <= ty1);

    int r0 = ty0 * TGX;
    int r1 = (ty0 + 1) * TGX;
    int r2 = (ty0 + 2) * TGX;

    // independent atomics first (latencies overlap), stores after
    int pa = atomicAdd(&g_count[r0 + tx0], 1);
    int pb = bx         ? atomicAdd(&g_count[r0 + tx1], 1) : CAP;
    int pc = by1        ? atomicAdd(&g_count[r1 + tx0], 1) : CAP;
    int pd = (by1 && bx)? atomicAdd(&g_count[r1 + tx1], 1) : CAP;
    int pe = by2        ? atomicAdd(&g_count[r2 + tx0], 1) : CAP;
    int pf = (by2 && bx)? atomicAdd(&g_count[r2 + tx1], 1) : CAP;

    float4 e = make_float4(xn, yn, cz, __int_as_float(p));
    if (pa < CAP) g_bin[(r0 + tx0) * CAP + pa] = e;
    if (pb < CAP) g_bin[(r0 + tx1) * CAP + pb] = e;
    if (pc < CAP) g_bin[(r1 + tx0) * CAP + pc] = e;
    if (pd < CAP) g_bin[(r1 + tx1) * CAP + pd] = e;
    if (pe < CAP) g_bin[(r2 + tx0) * CAP + pe] = e;
    if (pf < CAP) g_bin[(r2 + tx1) * CAP + pf] = e;
}

// -------------------------------------------------------------------
__device__ __forceinline__ u64 shfl_xor_u64(u64 v, int m) {
    u32 lo = (u32)v, hi = (u32)(v >> 32);
    lo = __shfl_xor_sync(0xffffffffu, lo, m);
    hi = __shfl_xor_sync(0xffffffffu, hi, m);
    return ((u64)hi << 32) | lo;
}

// In-register warp bitonic sort of NK*32 u64 keys, ascending.
// Element index i = k*32 + lane. Keys unique (slot bits), so ties can't occur.
template <int NK>
__device__ __forceinline__ void bitonic_warp(u64* V, int lane) {
    const int M = NK * 32;
#pragma unroll
    for (int ksz = 2; ksz <= M; ksz <<= 1) {
#pragma unroll
        for (int jsz = ksz >> 1; jsz > 0; jsz >>= 1) {
            if (jsz >= 32) {
                int j32 = jsz >> 5;
#pragma unroll
                for (int k = 0; k < NK; k++) {
                    if ((k & j32) == 0) {
                        int kb = k | j32;
                        bool up = (((k * 32) & ksz) == 0);   // ksz>=64 here
                        u64 a = V[k], b = V[kb];
                        if ((a > b) == up) { V[k] = b; V[kb] = a; }
                    }
                }
            } else {
#pragma unroll
                for (int k = 0; k < NK; k++) {
                    u64 p = shfl_xor_u64(V[k], jsz);
                    bool up = (((k * 32 + lane) & ksz) == 0);
                    bool lower = ((lane & jsz) == 0);
                    u64 mn = (V[k] < p) ? V[k] : p;
                    u64 mx = (V[k] < p) ? p : V[k];
                    V[k] = (lower == up) ? mn : mx;
                }
            }
        }
    }
}

// -------------------------------------------------------------------
// One warp per 8x4 tile; one lane per pixel. Warp-autonomous: no block barriers.
// Packed key: (z_bits<<23)|(idx<<8)|slot — ascending == (z, point-idx) order.
// PDL: cheap setup first, then cudaGridDependencySynchronize() before touching
// k_bin's outputs — overlaps this kernel's launch with k_bin's tail.
__global__ void __launch_bounds__(64) k_render(const float* __restrict__ feats,
                                               float* __restrict__ out) {
    int wrp = threadIdx.x >> 5, lane = threadIdx.x & 31;
    int tile = blockIdx.x * 2 + wrp;
    int txi = tile & (TGX - 1), tyi = tile >> 5;
    int w = (txi << TSHX) + (lane & 7);
    int h = (tyi << TSHY) + (lane >> 3);
    int pix = h * WW + w;
    float xs = 1.f - (2.f * w + 1.f) * (1.f / WW);
    float ys = 1.f - (2.f * h + 1.f) * (1.f / HH);

    cudaGridDependencySynchronize();   // wait for k_bin completion (PDL)

    int n = min(g_count[tile], CAP);
    if (lane == 0 && n) g_count[tile] = 0;   // re-arm for next graph replay

    if (n == 0) {                            // empty tile fast path
        out[pix * 3 + 0] = 0.f;
        out[pix * 3 + 1] = 0.f;
        out[pix * 3 + 2] = 0.f;
        out[HH * WW * 3 + pix] = 0.f;
        out[HH * WW * 4 + pix] = 0.f;
        return;
    }

    const float4* bin = g_bin + tile * CAP;

    __shared__ float4 s_sh[2][CAP];    // payload, load order
    __shared__ float4 s_sf[2][CAP];    // feature rgb, load order
    __shared__ float4 s_she[2][CAP];   // payload, sorted order
    __shared__ float4 s_sfe[2][CAP];   // features, sorted order
    float4* SH = s_sh[wrp];
    float4* SF = s_sf[wrp];
    float4* SHE = s_she[wrp];
    float4* SFE = s_sfe[wrp];

    // stage payload + build keys in registers + prefetch features
    u64 V[4];
#pragma unroll
    for (int k = 0; k < 4; k++) {
        int j = k * 32 + lane;
        u64 key = ~0ull;
        if (j < n) {
            float4 e = bin[j];
            SH[j] = e;
            int idx = __float_as_int(e.w);                 // < 32768
            key = ((u64)__float_as_uint(e.z) << 23) | ((u64)(u32)idx << 8) | (u32)j;
            const float* f = feats + 3 * idx;
            SF[j] = make_float4(f[0], f[1], f[2], 0.f);
        }
        V[k] = key;
    }
    __syncwarp();

    int nk = (n <= 64) ? 2 : 4;
    if (nk == 2) bitonic_warp<2>(V, lane);
    else         bitonic_warp<4>(V, lane);

    // scatter payload/features into sorted order straight from register keys
#pragma unroll
    for (int k = 0; k < 4; k++) {
        int i = k * 32 + lane;
        if (k < nk && i < n) {
            unsigned slot = (unsigned)(V[k] & 0xFF);
            SHE[i] = SH[slot];
            SFE[i] = SF[slot];
        }
    }
    __syncwarp();

    // streaming front-to-back composite; first KTOP hits == reference top-k
    // (z-ascending, lowest-idx tie-break); running T == cumprod.
    int cnt = 0;
    float T = 1.f, wsum = 0.f, wz = 0.f;
    float r = 0.f, g = 0.f, b = 0.f;
#pragma unroll 4
    for (int j = 0; j < n; j++) {
        float4 e = SHE[j];
        float dx = xs - e.x;
        float dy = ys - e.y;
        float d2 = fmaf(dx, dx, dy * dy);
        if (d2 < RR2 && cnt < KTOP) {
            float wgt = 1.f - d2 * (1.f / RR2);
            float4 f = SFE[j];
            float cw = wgt * T;
            r = fmaf(cw, f.x, r);
            g = fmaf(cw, f.y, g);
            b = fmaf(cw, f.z, b);
            wsum += wgt;
            wz = fmaf(wgt, e.z, wz);
            T *= (1.f - wgt);
            cnt++;
        }
    }

    out[pix * 3 + 0] = fminf(fmaxf(r, 0.f), 1.f);
    out[pix * 3 + 1] = fminf(fmaxf(g, 0.f), 1.f);
    out[pix * 3 + 2] = fminf(fmaxf(b, 0.f), 1.f);
    out[HH * WW * 3 + pix] = 1.f - T;                    // mask
    out[HH * WW * 4 + pix] = wz / fmaxf(wsum, EPSD);     // depth
}

extern "C" void kernel_launch(void* const* d_in, const int* in_sizes, int n_in,
                              void* d_out, int out_size) {
    const float* points    = (const float*)d_in[0];
    const float* features  = (const float*)d_in[1];
    const float* Rm        = (const float*)d_in[2];
    const float* Tv        = (const float*)d_in[3];
    const float* focal     = (const float*)d_in[4];
    const float* principal = (const float*)d_in[5];
    float* out = (float*)d_out;

    k_bin<<<(NP + 255) / 256, 256>>>(points, Rm, Tv, focal, principal);

    // k_render with programmatic dependent launch: overlap its launch/prologue
    // with k_bin's tail; cudaGridDependencySynchronize() inside provides order.
    cudaLaunchConfig_t cfg = {};
    cfg.gridDim  = dim3(NTILES / 2, 1, 1);
    cfg.blockDim = dim3(64, 1, 1);
    cudaLaunchAttribute attrs[1];
    attrs[0].id = cudaLaunchAttributeProgrammaticStreamSerialization;
    attrs[0].val.programmaticStreamSerializationAllowed = 1;
    cfg.attrs = attrs;
    cfg.numAttrs = 1;
    cudaLaunchKernelEx(&cfg, k_render, (const float*)features, (float*)out);
}